// round 3
// baseline (speedup 1.0000x reference)
#include <cuda_runtime.h>
#include <cstdint>

// ProbAttention (Informer ProbSparse) — B=2, L=4096, H=8, D=64, FACTOR=5 → u=U_part=45
//
// Pipeline (5 kernels, one stream, graph-capturable, no allocations):
//  1) idx_kernel     : bit-exact JAX *partitionable* threefry randint -> g_idx[4096*45]
//  2) m_kernel       : M[b,h,q] = max_s(Q·K[idx]) - sum_s(Q·K[idx])/L   (warp/q, 8 lanes per sample)
//  3) topk_kernel    : stable top-45 of M per (b,h) (selection, ties -> smaller index)
//  4) attn_kernel    : split-K flash attention for 45 selected queries per head
//  5) combine_kernel : merge split-K partials, write (B,45,H,D) output

#define BB 2
#define LL 4096
#define HH 8
#define DD 64
#define NBH 16          // B*H
#define UU 45
#define UP 48           // padded u
#define NSPLIT 16
#define KPB (LL / NSPLIT)   // 256 keys per block
#define TIL 32
#define NTILE (KPB / TIL)   // 8
#define NSAMP (LL * UU)     // 184320

__device__ int   g_idx[NSAMP];
__device__ float g_M[NBH * LL];
__device__ int   g_Mtop[NBH * UU];
__device__ float g_pm[NBH * NSPLIT * UP];
__device__ float g_pl[NBH * NSPLIT * UP];
__device__ float g_pacc[NBH * NSPLIT * UP * DD];

// ---------------------------------------------------------------- threefry
__device__ __forceinline__ uint32_t rotl32(uint32_t x, int n) {
    return (x << n) | (x >> (32 - n));
}

__device__ __forceinline__ void threefry2x32(uint32_t k0, uint32_t k1,
                                             uint32_t c0, uint32_t c1,
                                             uint32_t& o0, uint32_t& o1) {
    uint32_t ks0 = k0, ks1 = k1, ks2 = k0 ^ k1 ^ 0x1BD11BDAu;
    uint32_t x0 = c0 + ks0, x1 = c1 + ks1;
#define TF_R(r) { x0 += x1; x1 = rotl32(x1, r); x1 ^= x0; }
    TF_R(13) TF_R(15) TF_R(26) TF_R(6)
    x0 += ks1; x1 += ks2 + 1u;
    TF_R(17) TF_R(29) TF_R(16) TF_R(24)
    x0 += ks2; x1 += ks0 + 2u;
    TF_R(13) TF_R(15) TF_R(26) TF_R(6)
    x0 += ks0; x1 += ks1 + 3u;
    TF_R(17) TF_R(29) TF_R(16) TF_R(24)
    x0 += ks1; x1 += ks2 + 4u;
    TF_R(13) TF_R(15) TF_R(26) TF_R(6)
    x0 += ks2; x1 += ks0 + 5u;
#undef TF_R
    o0 = x0; o1 = x1;
}

// idx = jax.random.randint(key(1), (4096,45), 0, 4096) under MODERN JAX
// (jax_threefry_partitionable = True, the current default):
//   key(1) = (0,1)
//   split (partitionable/fold-like): child i = threefry2x32(key, (hi(i), lo(i)));
//     k2 = split(key)[1] = threefry2x32((0,1), (0,1)) -> (s0, s1)
//   random_bits (partitionable, 32-bit): element j has 64-bit counter j;
//     bits[j] = x0 ^ x1 of threefry2x32(k2, (0, j))   (XOR-fold of both outputs)
//   span = 4096 is a power of two -> multiplier = (2^16 mod 4096)^2 mod 4096 = 0,
//     so higher_bits vanish and idx[j] = bits[j] & 4095.
__global__ __launch_bounds__(256) void idx_kernel() {
    int j = blockIdx.x * 256 + threadIdx.x;
    if (j >= NSAMP) return;
    uint32_t s0, s1;
    threefry2x32(0u, 1u, 0u, 1u, s0, s1);     // k2 (constant; cheap per thread)
    uint32_t o0, o1;
    threefry2x32(s0, s1, 0u, (uint32_t)j, o0, o1);
    g_idx[j] = (int)((o0 ^ o1) & 4095u);
}

// ---------------------------------------------------------------- sparse measure M
// one warp per (b,h,q); 4 groups of 8 lanes, each group computes one sample dot
__global__ __launch_bounds__(256) void m_kernel(const float* __restrict__ Q,
                                                const float* __restrict__ K) {
    int w    = blockIdx.x * 8 + (threadIdx.x >> 5);
    int lane = threadIdx.x & 31;
    int bh = w >> 12;
    int q  = w & 4095;
    int b = bh >> 3, h = bh & 7;
    int g = lane >> 3, l8 = lane & 7;

    const float* qp = Q + ((size_t)(b * LL + q) * HH + h) * DD + l8 * 8;
    float4 qa = *(const float4*)qp;
    float4 qb = *(const float4*)(qp + 4);
    const float* kbase = K + ((size_t)(b * LL) * HH + h) * DD;
    const int* idxp = g_idx + q * UU;

    float mx = -3.4e38f, sm = 0.f;
#pragma unroll 1
    for (int t = 0; t < 12; ++t) {
        int s = t * 4 + g;
        bool valid = (s < UU);
        int i = valid ? idxp[s] : 0;
        const float* kp = kbase + (size_t)i * (HH * DD) + l8 * 8;
        float4 ka = *(const float4*)kp;
        float4 kb = *(const float4*)(kp + 4);
        float p = qa.x * ka.x + qa.y * ka.y + qa.z * ka.z + qa.w * ka.w
                + qb.x * kb.x + qb.y * kb.y + qb.z * kb.z + qb.w * kb.w;
        p += __shfl_xor_sync(0xffffffffu, p, 1);
        p += __shfl_xor_sync(0xffffffffu, p, 2);
        p += __shfl_xor_sync(0xffffffffu, p, 4);
        if (valid) { mx = fmaxf(mx, p); sm += p; }
    }
    mx = fmaxf(mx, __shfl_xor_sync(0xffffffffu, mx, 8));
    sm +=           __shfl_xor_sync(0xffffffffu, sm, 8);
    mx = fmaxf(mx, __shfl_xor_sync(0xffffffffu, mx, 16));
    sm +=           __shfl_xor_sync(0xffffffffu, sm, 16);
    if (lane == 0) g_M[bh * LL + q] = mx - sm * (1.0f / LL);
}

// ---------------------------------------------------------------- stable top-45
__global__ __launch_bounds__(256) void topk_kernel() {
    __shared__ float vals[LL];
    __shared__ float rv[256];
    __shared__ int   ri[256];
    int bh = blockIdx.x;
    int t = threadIdx.x;
    const float NEG_INF = __int_as_float(0xff800000);
    for (int i = t; i < LL; i += 256) vals[i] = g_M[bh * LL + i];
    __syncthreads();
    for (int p = 0; p < UU; ++p) {
        float bv = NEG_INF;
        int   bi = 0x7fffffff;
        for (int i = t; i < LL; i += 256) {
            float v = vals[i];
            if (v > bv || (v == bv && i < bi)) { bv = v; bi = i; }
        }
        rv[t] = bv; ri[t] = bi;
        __syncthreads();
        for (int off = 128; off > 0; off >>= 1) {
            if (t < off) {
                float v2 = rv[t + off]; int i2 = ri[t + off];
                if (v2 > rv[t] || (v2 == rv[t] && i2 < ri[t])) { rv[t] = v2; ri[t] = i2; }
            }
            __syncthreads();
        }
        if (t == 0) {
            g_Mtop[bh * UU + p] = ri[0];
            vals[ri[0]] = NEG_INF;
        }
        __syncthreads();
    }
}

// ---------------------------------------------------------------- split-K flash attention
// block: (b,h, key-split). 256 thr = 16x16; thread owns 3 u-rows x (2 keys | 4 dims)
__global__ __launch_bounds__(256) void attn_kernel(const float* __restrict__ Q,
                                                   const float* __restrict__ K,
                                                   const float* __restrict__ V,
                                                   const int*   __restrict__ amask) {
    __shared__ float Qs[UP][68];
    __shared__ float Ks[TIL][68];
    __shared__ float Vs[TIL][68];
    __shared__ float Ss[UP][36];
    __shared__ float smm[UP], sml[UP], sma[UP];

    int bh = blockIdx.x >> 4;
    int sp = blockIdx.x & 15;
    int b = bh >> 3, h = bh & 7;
    int t = threadIdx.x;
    int tx = t & 15, ty = t >> 4;
    int u0 = ty * 3;

    for (int i = t; i < UP * DD; i += 256) {
        int u = i >> 6, d = i & 63;
        float v = 0.f;
        if (u < UU) {
            int qi = g_Mtop[bh * UU + u];
            v = Q[((size_t)(b * LL + qi) * HH + h) * DD + d] * 0.125f;  // 1/sqrt(64)
        }
        Qs[u][d] = v;
    }
    if (t < UP) { smm[t] = -1e30f; sml[t] = 0.f; }

    float4 acc[3];
    acc[0] = make_float4(0.f, 0.f, 0.f, 0.f);
    acc[1] = acc[0]; acc[2] = acc[0];
    __syncthreads();

    int j0base = sp * KPB;
    for (int tile = 0; tile < NTILE; ++tile) {
        int j0 = j0base + tile * TIL;
        {
            const float* kb = K + ((size_t)(b * LL + j0) * HH + h) * DD;
            const float* vb = V + ((size_t)(b * LL + j0) * HH + h) * DD;
#pragma unroll
            for (int r = 0; r < 2; ++r) {
                int idx = t + 256 * r;     // 0..511 float4s of a 32x64 tile
                int j = idx >> 4, c4 = idx & 15;
                *(float4*)&Ks[j][c4 * 4] = *(const float4*)(kb + (size_t)j * (HH * DD) + c4 * 4);
                *(float4*)&Vs[j][c4 * 4] = *(const float4*)(vb + (size_t)j * (HH * DD) + c4 * 4);
            }
        }
        __syncthreads();

        // scores: 3u x 2j per thread (j = tx, tx+16)
        float s[3][2] = {};
#pragma unroll
        for (int d4 = 0; d4 < 16; ++d4) {
            float4 kv0 = *(const float4*)&Ks[tx][d4 * 4];
            float4 kv1 = *(const float4*)&Ks[tx + 16][d4 * 4];
#pragma unroll
            for (int uu = 0; uu < 3; ++uu) {
                float4 qv = *(const float4*)&Qs[u0 + uu][d4 * 4];
                s[uu][0] += qv.x * kv0.x + qv.y * kv0.y + qv.z * kv0.z + qv.w * kv0.w;
                s[uu][1] += qv.x * kv1.x + qv.y * kv1.y + qv.z * kv1.z + qv.w * kv1.w;
            }
        }
#pragma unroll
        for (int jj = 0; jj < 2; ++jj) {
            int jl = tx + 16 * jj;
            int mk = amask[b * LL + j0 + jl];
#pragma unroll
            for (int uu = 0; uu < 3; ++uu)
                Ss[u0 + uu][jl] = mk ? s[uu][jj] : -1e30f;
        }
        __syncthreads();

        // online softmax row update (one thread per u-row)
        if (t < UP) {
            int u = t;
            float mold = smm[u];
            float mnew = mold;
#pragma unroll
            for (int j = 0; j < TIL; ++j) mnew = fmaxf(mnew, Ss[u][j]);
            float alpha = __expf(mold - mnew);
            float lsum = 0.f;
#pragma unroll
            for (int j = 0; j < TIL; ++j) {
                float e = __expf(Ss[u][j] - mnew);
                Ss[u][j] = e;
                lsum += e;
            }
            sml[u] = sml[u] * alpha + lsum;
            smm[u] = mnew;
            sma[u] = alpha;
        }
        __syncthreads();

        // rescale + P@V: thread owns (3u, d=4*tx..4*tx+3)
#pragma unroll
        for (int uu = 0; uu < 3; ++uu) {
            float a = sma[u0 + uu];
            acc[uu].x *= a; acc[uu].y *= a; acc[uu].z *= a; acc[uu].w *= a;
        }
#pragma unroll
        for (int j4 = 0; j4 < TIL / 4; ++j4) {
            float4 vr0 = *(const float4*)&Vs[j4 * 4 + 0][tx * 4];
            float4 vr1 = *(const float4*)&Vs[j4 * 4 + 1][tx * 4];
            float4 vr2 = *(const float4*)&Vs[j4 * 4 + 2][tx * 4];
            float4 vr3 = *(const float4*)&Vs[j4 * 4 + 3][tx * 4];
#pragma unroll
            for (int uu = 0; uu < 3; ++uu) {
                float4 sv = *(const float4*)&Ss[u0 + uu][j4 * 4];
                acc[uu].x += sv.x * vr0.x + sv.y * vr1.x + sv.z * vr2.x + sv.w * vr3.x;
                acc[uu].y += sv.x * vr0.y + sv.y * vr1.y + sv.z * vr2.y + sv.w * vr3.y;
                acc[uu].z += sv.x * vr0.z + sv.y * vr1.z + sv.z * vr2.z + sv.w * vr3.z;
                acc[uu].w += sv.x * vr0.w + sv.y * vr1.w + sv.z * vr2.w + sv.w * vr3.w;
            }
        }
        __syncthreads();
    }

    size_t base = (size_t)(bh * NSPLIT + sp) * UP;
#pragma unroll
    for (int uu = 0; uu < 3; ++uu)
        *(float4*)&g_pacc[(base + u0 + uu) * DD + tx * 4] = acc[uu];
    if (t < UP) { g_pm[base + t] = smm[t]; g_pl[base + t] = sml[t]; }
}

// ---------------------------------------------------------------- combine split-K partials
__global__ __launch_bounds__(256) void combine_kernel(float* __restrict__ out) {
    int w = blockIdx.x * 8 + ((int)threadIdx.x >> 5);
    if (w >= NBH * UU) return;
    int lane = threadIdx.x & 31;
    int bh = w / UU, u = w % UU;
    int b = bh >> 3, h = bh & 7;

    float m = -3.4e38f;
#pragma unroll
    for (int i = 0; i < NSPLIT; ++i)
        m = fmaxf(m, g_pm[(bh * NSPLIT + i) * UP + u]);

    float Lsum = 0.f, o0 = 0.f, o1 = 0.f;
#pragma unroll 1
    for (int i = 0; i < NSPLIT; ++i) {
        size_t pb = (size_t)(bh * NSPLIT + i) * UP + u;
        float wgt = __expf(g_pm[pb] - m);
        Lsum += g_pl[pb] * wgt;
        o0 += g_pacc[pb * DD + lane] * wgt;
        o1 += g_pacc[pb * DD + lane + 32] * wgt;
    }
    float inv = 1.0f / Lsum;
    size_t ob = ((size_t)(b * UU + u) * HH + h) * DD;
    out[ob + lane]      = o0 * inv;
    out[ob + lane + 32] = o1 * inv;
}

// ----------------------------------------------------------------
extern "C" void kernel_launch(void* const* d_in, const int* in_sizes, int n_in,
                              void* d_out, int out_size) {
    const float* Q    = (const float*)d_in[0];
    const float* K    = (const float*)d_in[1];
    const float* V    = (const float*)d_in[2];
    const int*   mask = (const int*)d_in[3];
    float* out = (float*)d_out;

    idx_kernel<<<(NSAMP + 255) / 256, 256>>>();
    m_kernel<<<NBH * LL / 8, 256>>>(Q, K);
    topk_kernel<<<NBH, 256>>>();
    attn_kernel<<<NBH * NSPLIT, 256>>>(Q, K, V, mask);
    combine_kernel<<<(NBH * UU + 7) / 8, 256>>>(out);
}

// round 4
// speedup vs baseline: 1.1068x; 1.1068x over previous
#include <cuda_runtime.h>
#include <cstdint>

// ProbAttention (Informer ProbSparse) — B=2, L=4096, H=8, D=64, FACTOR=5 → u=U_part=45

#define BB 2
#define LL 4096
#define HH 8
#define DD 64
#define NBH 16          // B*H
#define UU 45
#define UP 48           // padded u
#define NSPLIT 64
#define KPB (LL / NSPLIT)   // 64 keys per block
#define TIL 32
#define NTILE (KPB / TIL)   // 2
#define NSAMP (LL * UU)     // 184320

__device__ int   g_idx[NSAMP];
__device__ float g_M[NBH * LL];
__device__ int   g_Mtop[NBH * UU];
__device__ float g_pm[NBH * NSPLIT * UP];
__device__ float g_pl[NBH * NSPLIT * UP];
__device__ float g_pacc[NBH * NSPLIT * UP * DD];

// ---------------------------------------------------------------- threefry
__device__ __forceinline__ uint32_t rotl32(uint32_t x, int n) {
    return (x << n) | (x >> (32 - n));
}

__device__ __forceinline__ void threefry2x32(uint32_t k0, uint32_t k1,
                                             uint32_t c0, uint32_t c1,
                                             uint32_t& o0, uint32_t& o1) {
    uint32_t ks0 = k0, ks1 = k1, ks2 = k0 ^ k1 ^ 0x1BD11BDAu;
    uint32_t x0 = c0 + ks0, x1 = c1 + ks1;
#define TF_R(r) { x0 += x1; x1 = rotl32(x1, r); x1 ^= x0; }
    TF_R(13) TF_R(15) TF_R(26) TF_R(6)
    x0 += ks1; x1 += ks2 + 1u;
    TF_R(17) TF_R(29) TF_R(16) TF_R(24)
    x0 += ks2; x1 += ks0 + 2u;
    TF_R(13) TF_R(15) TF_R(26) TF_R(6)
    x0 += ks0; x1 += ks1 + 3u;
    TF_R(17) TF_R(29) TF_R(16) TF_R(24)
    x0 += ks1; x1 += ks2 + 4u;
    TF_R(13) TF_R(15) TF_R(26) TF_R(6)
    x0 += ks2; x1 += ks0 + 5u;
#undef TF_R
    o0 = x0; o1 = x1;
}

// Modern JAX partitionable threefry:
//   k2 = split(key(1))[1] = threefry((0,1),(0,1)); bits[j] = fold_in xor of
//   threefry(k2,(0,j)); idx[j] = bits[j] & 4095 (span 4096 kills multiplier).
__global__ __launch_bounds__(256) void idx_kernel() {
    int j = blockIdx.x * 256 + threadIdx.x;
    if (j >= NSAMP) return;
    uint32_t s0, s1;
    threefry2x32(0u, 1u, 0u, 1u, s0, s1);     // constant-folded
    uint32_t o0, o1;
    threefry2x32(s0, s1, 0u, (uint32_t)j, o0, o1);
    g_idx[j] = (int)((o0 ^ o1) & 4095u);
}

// ---------------------------------------------------------------- sparse measure M
// one warp per (b,h,q); 4 groups of 8 lanes; 2 samples per group per iter (MLP=4)
__global__ __launch_bounds__(256) void m_kernel(const float* __restrict__ Q,
                                                const float* __restrict__ K) {
    int w    = blockIdx.x * 8 + (threadIdx.x >> 5);
    int lane = threadIdx.x & 31;
    int bh = w >> 12;
    int q  = w & 4095;
    int b = bh >> 3, h = bh & 7;
    int g = lane >> 3, l8 = lane & 7;

    const float* qp = Q + ((size_t)(b * LL + q) * HH + h) * DD + l8 * 8;
    float4 qa = *(const float4*)qp;
    float4 qb = *(const float4*)(qp + 4);
    const float* kbase = K + ((size_t)(b * LL) * HH + h) * DD + l8 * 8;
    const int* idxp = g_idx + q * UU;

    float mx = -3.4e38f, sm = 0.f;
#pragma unroll 1
    for (int t = 0; t < 6; ++t) {
        int s0 = t * 8 + g;
        int s1 = s0 + 4;
        bool v0 = (s0 < UU), v1 = (s1 < UU);
        int i0 = v0 ? idxp[s0] : 0;
        int i1 = v1 ? idxp[s1] : 0;
        const float* kp0 = kbase + (size_t)i0 * (HH * DD);
        const float* kp1 = kbase + (size_t)i1 * (HH * DD);
        float4 k0a = *(const float4*)kp0;
        float4 k0b = *(const float4*)(kp0 + 4);
        float4 k1a = *(const float4*)kp1;
        float4 k1b = *(const float4*)(kp1 + 4);
        float p0 = qa.x * k0a.x + qa.y * k0a.y + qa.z * k0a.z + qa.w * k0a.w
                 + qb.x * k0b.x + qb.y * k0b.y + qb.z * k0b.z + qb.w * k0b.w;
        float p1 = qa.x * k1a.x + qa.y * k1a.y + qa.z * k1a.z + qa.w * k1a.w
                 + qb.x * k1b.x + qb.y * k1b.y + qb.z * k1b.z + qb.w * k1b.w;
        p0 += __shfl_xor_sync(0xffffffffu, p0, 1);
        p1 += __shfl_xor_sync(0xffffffffu, p1, 1);
        p0 += __shfl_xor_sync(0xffffffffu, p0, 2);
        p1 += __shfl_xor_sync(0xffffffffu, p1, 2);
        p0 += __shfl_xor_sync(0xffffffffu, p0, 4);
        p1 += __shfl_xor_sync(0xffffffffu, p1, 4);
        if (v0) { mx = fmaxf(mx, p0); sm += p0; }
        if (v1) { mx = fmaxf(mx, p1); sm += p1; }
    }
    mx = fmaxf(mx, __shfl_xor_sync(0xffffffffu, mx, 8));
    sm +=           __shfl_xor_sync(0xffffffffu, sm, 8);
    mx = fmaxf(mx, __shfl_xor_sync(0xffffffffu, mx, 16));
    sm +=           __shfl_xor_sync(0xffffffffu, sm, 16);
    if (lane == 0) g_M[bh * LL + q] = mx - sm * (1.0f / LL);
}

// ---------------------------------------------------------------- stable top-45
// 1024 threads, 4 values in registers; 2 barriers per pass.
__global__ __launch_bounds__(1024) void topk_kernel() {
    __shared__ float wv[32];
    __shared__ int   wi[32];
    __shared__ int   s_win;
    int bh = blockIdx.x;
    int t = threadIdx.x;
    int lane = t & 31, warp = t >> 5;
    const float NEG_INF = -3.4e38f;

    float v[4];
    int base = t * 4;
#pragma unroll
    for (int j = 0; j < 4; ++j) v[j] = g_M[bh * LL + base + j];
    int removed = 0;

    for (int p = 0; p < UU; ++p) {
        float bv = NEG_INF;
        int   bi = 0x7fffffff;
#pragma unroll
        for (int j = 0; j < 4; ++j) {
            if (!((removed >> j) & 1)) {
                float vj = v[j];
                if (vj > bv) { bv = vj; bi = base + j; }   // ascending j keeps smallest idx on ties
            }
        }
#pragma unroll
        for (int off = 16; off > 0; off >>= 1) {
            float ov = __shfl_xor_sync(0xffffffffu, bv, off);
            int   oi = __shfl_xor_sync(0xffffffffu, bi, off);
            if (ov > bv || (ov == bv && oi < bi)) { bv = ov; bi = oi; }
        }
        if (lane == 0) { wv[warp] = bv; wi[warp] = bi; }
        __syncthreads();
        if (warp == 0) {
            float fv = wv[lane];
            int   fi = wi[lane];
#pragma unroll
            for (int off = 16; off > 0; off >>= 1) {
                float ov = __shfl_xor_sync(0xffffffffu, fv, off);
                int   oi = __shfl_xor_sync(0xffffffffu, fi, off);
                if (ov > fv || (ov == fv && oi < fi)) { fv = ov; fi = oi; }
            }
            if (lane == 0) {
                g_Mtop[bh * UU + p] = fi;
                s_win = fi;
            }
        }
        __syncthreads();
        int win = s_win;
        if ((win >> 2) == t) removed |= 1 << (win & 3);
    }
}

// ---------------------------------------------------------------- split-K flash attention
// block: (b,h, key-split). 256 thr = 16x16; thread owns 3 u-rows x (2 keys | 4 dims)
__global__ __launch_bounds__(256) void attn_kernel(const float* __restrict__ Q,
                                                   const float* __restrict__ K,
                                                   const float* __restrict__ V,
                                                   const int*   __restrict__ amask) {
    __shared__ float Qs[UP][68];
    __shared__ float Ks[TIL][68];
    __shared__ float Vs[TIL][68];
    __shared__ float Ss[UP][36];
    __shared__ float smm[UP], sml[UP], sma[UP];

    int bh = blockIdx.x / NSPLIT;
    int sp = blockIdx.x % NSPLIT;
    int b = bh >> 3, h = bh & 7;
    int t = threadIdx.x;
    int tx = t & 15, ty = t >> 4;
    int u0 = ty * 3;

    for (int i = t; i < UP * DD; i += 256) {
        int u = i >> 6, d = i & 63;
        float v = 0.f;
        if (u < UU) {
            int qi = g_Mtop[bh * UU + u];
            v = Q[((size_t)(b * LL + qi) * HH + h) * DD + d] * 0.125f;  // 1/sqrt(64)
        }
        Qs[u][d] = v;
    }
    if (t < UP) { smm[t] = -1e30f; sml[t] = 0.f; }

    float4 acc[3];
    acc[0] = make_float4(0.f, 0.f, 0.f, 0.f);
    acc[1] = acc[0]; acc[2] = acc[0];
    __syncthreads();

    int j0base = sp * KPB;
#pragma unroll 1
    for (int tile = 0; tile < NTILE; ++tile) {
        int j0 = j0base + tile * TIL;
        {
            const float* kb = K + ((size_t)(b * LL + j0) * HH + h) * DD;
            const float* vb = V + ((size_t)(b * LL + j0) * HH + h) * DD;
#pragma unroll
            for (int r = 0; r < 2; ++r) {
                int idx = t + 256 * r;     // 0..511 float4s of a 32x64 tile
                int j = idx >> 4, c4 = idx & 15;
                *(float4*)&Ks[j][c4 * 4] = *(const float4*)(kb + (size_t)j * (HH * DD) + c4 * 4);
                *(float4*)&Vs[j][c4 * 4] = *(const float4*)(vb + (size_t)j * (HH * DD) + c4 * 4);
            }
        }
        __syncthreads();

        // scores: 3u x 2j per thread (j = tx, tx+16)
        float s[3][2] = {};
#pragma unroll
        for (int d4 = 0; d4 < 16; ++d4) {
            float4 kv0 = *(const float4*)&Ks[tx][d4 * 4];
            float4 kv1 = *(const float4*)&Ks[tx + 16][d4 * 4];
#pragma unroll
            for (int uu = 0; uu < 3; ++uu) {
                float4 qv = *(const float4*)&Qs[u0 + uu][d4 * 4];
                s[uu][0] += qv.x * kv0.x + qv.y * kv0.y + qv.z * kv0.z + qv.w * kv0.w;
                s[uu][1] += qv.x * kv1.x + qv.y * kv1.y + qv.z * kv1.z + qv.w * kv1.w;
            }
        }
#pragma unroll
        for (int jj = 0; jj < 2; ++jj) {
            int jl = tx + 16 * jj;
            int mk = amask[b * LL + j0 + jl];
#pragma unroll
            for (int uu = 0; uu < 3; ++uu)
                Ss[u0 + uu][jl] = mk ? s[uu][jj] : -1e30f;
        }
        __syncthreads();

        // online softmax row update (one thread per u-row)
        if (t < UP) {
            int u = t;
            float mold = smm[u];
            float mnew = mold;
#pragma unroll
            for (int j = 0; j < TIL; ++j) mnew = fmaxf(mnew, Ss[u][j]);
            float alpha = __expf(mold - mnew);
            float lsum = 0.f;
#pragma unroll
            for (int j = 0; j < TIL; ++j) {
                float e = __expf(Ss[u][j] - mnew);
                Ss[u][j] = e;
                lsum += e;
            }
            sml[u] = sml[u] * alpha + lsum;
            smm[u] = mnew;
            sma[u] = alpha;
        }
        __syncthreads();

        // rescale + P@V: thread owns (3u, d=4*tx..4*tx+3)
#pragma unroll
        for (int uu = 0; uu < 3; ++uu) {
            float a = sma[u0 + uu];
            acc[uu].x *= a; acc[uu].y *= a; acc[uu].z *= a; acc[uu].w *= a;
        }
#pragma unroll
        for (int j4 = 0; j4 < TIL / 4; ++j4) {
            float4 vr0 = *(const float4*)&Vs[j4 * 4 + 0][tx * 4];
            float4 vr1 = *(const float4*)&Vs[j4 * 4 + 1][tx * 4];
            float4 vr2 = *(const float4*)&Vs[j4 * 4 + 2][tx * 4];
            float4 vr3 = *(const float4*)&Vs[j4 * 4 + 3][tx * 4];
#pragma unroll
            for (int uu = 0; uu < 3; ++uu) {
                float4 sv = *(const float4*)&Ss[u0 + uu][j4 * 4];
                acc[uu].x += sv.x * vr0.x + sv.y * vr1.x + sv.z * vr2.x + sv.w * vr3.x;
                acc[uu].y += sv.x * vr0.y + sv.y * vr1.y + sv.z * vr2.y + sv.w * vr3.y;
                acc[uu].z += sv.x * vr0.z + sv.y * vr1.z + sv.z * vr2.z + sv.w * vr3.z;
                acc[uu].w += sv.x * vr0.w + sv.y * vr1.w + sv.z * vr2.w + sv.w * vr3.w;
            }
        }
        __syncthreads();
    }

    size_t base = (size_t)(bh * NSPLIT + sp) * UP;
#pragma unroll
    for (int uu = 0; uu < 3; ++uu)
        *(float4*)&g_pacc[(base + u0 + uu) * DD + tx * 4] = acc[uu];
    if (t < UP) { g_pm[base + t] = smm[t]; g_pl[base + t] = sml[t]; }
}

// ---------------------------------------------------------------- combine split-K partials
__global__ __launch_bounds__(256) void combine_kernel(float* __restrict__ out) {
    int w = blockIdx.x * 8 + ((int)threadIdx.x >> 5);
    if (w >= NBH * UU) return;
    int lane = threadIdx.x & 31;
    int bh = w / UU, u = w % UU;
    int b = bh >> 3, h = bh & 7;

    float m = -3.4e38f;
#pragma unroll 8
    for (int i = 0; i < NSPLIT; ++i)
        m = fmaxf(m, g_pm[(bh * NSPLIT + i) * UP + u]);

    float Lsum = 0.f, o0 = 0.f, o1 = 0.f;
#pragma unroll 4
    for (int i = 0; i < NSPLIT; ++i) {
        size_t pb = (size_t)(bh * NSPLIT + i) * UP + u;
        float wgt = __expf(g_pm[pb] - m);
        Lsum += g_pl[pb] * wgt;
        o0 += g_pacc[pb * DD + lane] * wgt;
        o1 += g_pacc[pb * DD + lane + 32] * wgt;
    }
    float inv = 1.0f / Lsum;
    size_t ob = ((size_t)(b * UU + u) * HH + h) * DD;
    out[ob + lane]      = o0 * inv;
    out[ob + lane + 32] = o1 * inv;
}

// ----------------------------------------------------------------
extern "C" void kernel_launch(void* const* d_in, const int* in_sizes, int n_in,
                              void* d_out, int out_size) {
    const float* Q    = (const float*)d_in[0];
    const float* K    = (const float*)d_in[1];
    const float* V    = (const float*)d_in[2];
    const int*   mask = (const int*)d_in[3];
    float* out = (float*)d_out;

    idx_kernel<<<(NSAMP + 255) / 256, 256>>>();
    m_kernel<<<NBH * LL / 8, 256>>>(Q, K);
    topk_kernel<<<NBH, 1024>>>();
    attn_kernel<<<NBH * NSPLIT, 256>>>(Q, K, V, mask);
    combine_kernel<<<(NBH * UU + 7) / 8, 256>>>(out);
}